// round 16
// baseline (speedup 1.0000x reference)
#include <cuda_runtime.h>
#include <cuda_fp16.h>
#include <cstdint>

#define H_     128
#define CIN_   64
#define O_     16
#define F2_    16
#define NT_    32768
#define TILES_ 2
#define NTH_   512
#define EPS_   1e-5f
#define SLOPE_ 0.01f

// ---- device scratch (static allocation; no runtime mallocs) ----
__device__ uint4 g_wf0[O_][4 * 8 * 32];               // weight fragments
__device__ uint4 g_wf1[O_][8 * 8 * 32];
__device__ uint4 g_wf2[O_][8 * 32];
__device__ uint4 g_xf[(size_t)(NT_ / 16) * 128];      // x fragments, 4MB
__device__ uint4 g_scrh4[(size_t)O_ * NT_ * 2];       // fp16 scratch [o][t][f], 16MB
__device__ int   g_cnt[64];                           // per-token-column arrival counters

// ---- main-kernel shared memory byte offsets ----
#define SM_W0  0          // [4][8][32] uint4 = 16384
#define SM_W1  16384      // [8][8][32] uint4 = 32768
#define SM_W2  49152      // [8][1][32] uint4 = 4096
#define SM_B   53248      // b0(128), b1(128), b2(16)
#define SM_GE0 54400      // 64 x float4
#define SM_GE1 55424      // 64 x float4
// transpose staging (reuses whole region after GEMMs): 64 tok x 260 floats
#define SMEM_BYTES (64 * 260 * 4)   // 66560 >= 56448

__device__ __forceinline__ float leaky_(float v) { return fmaxf(v, SLOPE_ * v); }

__device__ __forceinline__ uint32_t pack2h(float y0, float y1) {
    uint32_t h;
    asm("cvt.rn.f16x2.f32 %0, %1, %2;" : "=r"(h) : "f"(y1), "f"(y0));
    return h;
}

#define MMA2(dd, aa, b0, b1)                                                   \
    asm volatile("mma.sync.aligned.m16n8k16.row.col.f32.f16.f16.f32 "         \
                 "{%0,%1,%2,%3}, {%4,%5,%6,%7}, {%8,%9}, {%0,%1,%2,%3};"      \
                 : "+f"((dd)[0]), "+f"((dd)[1]), "+f"((dd)[2]), "+f"((dd)[3]) \
                 : "r"((aa)[0]), "r"((aa)[1]), "r"((aa)[2]), "r"((aa)[3]),    \
                   "r"(b0), "r"(b1))

// ---------- fused prep kernel ----------
// blocks [0,64): weight fragment conversion (4 parts per o) + counter reset
// blocks [64,576): x conversion (64 tokens per block)
__global__ __launch_bounds__(256, 1)
void film_prep_kernel(const float* __restrict__ W0, const float* __restrict__ W1,
                      const float* __restrict__ W2, const float* __restrict__ x) {
    const int tid = threadIdx.x;
    if (blockIdx.x < 64) {
        if (tid == 0) g_cnt[blockIdx.x] = 0;   // reset arrival counter (per replay)
        const int o = blockIdx.x >> 2;
        const int part = blockIdx.x & 3;
        const float* w0 = W0 + (size_t)o * H_ * CIN_;
        {
            int i = part * 256 + tid;
            int ln = i & 31, jp = (i >> 5) & 7, ss = i >> 8;
            int gg = ln >> 2, tt = ln & 3;
            int n0 = 8 * (2 * jp) + gg, n1 = n0 + 8, k0 = 16 * ss + 2 * tt;
            g_wf0[o][i] = make_uint4(pack2h(w0[n0 * 64 + k0],     w0[n0 * 64 + k0 + 1]),
                                     pack2h(w0[n0 * 64 + k0 + 8], w0[n0 * 64 + k0 + 9]),
                                     pack2h(w0[n1 * 64 + k0],     w0[n1 * 64 + k0 + 1]),
                                     pack2h(w0[n1 * 64 + k0 + 8], w0[n1 * 64 + k0 + 9]));
        }
        const float* w1 = W1 + (size_t)o * H_ * H_;
        for (int i = part * 512 + tid; i < (part + 1) * 512; i += 256) {
            int ln = i & 31, jp = (i >> 5) & 7, ss = i >> 8;
            int gg = ln >> 2, tt = ln & 3;
            int n0 = 8 * (2 * jp) + gg, n1 = n0 + 8, k0 = 16 * ss + 2 * tt;
            g_wf1[o][i] = make_uint4(pack2h(w1[n0 * 128 + k0],     w1[n0 * 128 + k0 + 1]),
                                     pack2h(w1[n0 * 128 + k0 + 8], w1[n0 * 128 + k0 + 9]),
                                     pack2h(w1[n1 * 128 + k0],     w1[n1 * 128 + k0 + 1]),
                                     pack2h(w1[n1 * 128 + k0 + 8], w1[n1 * 128 + k0 + 9]));
        }
        const float* w2 = W2 + (size_t)o * F2_ * H_;
        if (part == 0) {
            int i = tid;
            int ln = i & 31, ss = i >> 5;
            int gg = ln >> 2, tt = ln & 3;
            int n0 = gg, n1 = gg + 8, k0 = 16 * ss + 2 * tt;
            g_wf2[o][i] = make_uint4(pack2h(w2[n0 * 128 + k0],     w2[n0 * 128 + k0 + 1]),
                                     pack2h(w2[n0 * 128 + k0 + 8], w2[n0 * 128 + k0 + 9]),
                                     pack2h(w2[n1 * 128 + k0],     w2[n1 * 128 + k0 + 1]),
                                     pack2h(w2[n1 * 128 + k0 + 8], w2[n1 * 128 + k0 + 9]));
        }
    } else {
        // ---- x conversion: 64 tokens per block, row-major fp32 -> fragment fp16 ----
        __shared__ float sx[64 * 64];
        const int blk = blockIdx.x - 64;
        const float4* x4 = (const float4*)(x + (size_t)blk * 64 * 64);
        float4* s4 = (float4*)sx;
#pragma unroll
        for (int p = 0; p < 4; p++) s4[p * 256 + tid] = x4[p * 256 + tid];
        __syncthreads();
        const int tb0 = blk * 4;
#pragma unroll
        for (int p = 0; p < 2; p++) {
            int idx = p * 256 + tid;
            int tb = idx >> 7, rest = idx & 127, s = rest >> 5, lane = rest & 31;
            int g = lane >> 2, t = lane & 3;
            int k0 = 16 * s + 2 * t;
            const float* r0 = sx + (tb * 16 + g) * 64;
            const float* r1 = sx + (tb * 16 + g + 8) * 64;
            g_xf[(size_t)(tb0 + tb) * 128 + s * 32 + lane] =
                make_uint4(pack2h(r0[k0], r0[k0 + 1]),     pack2h(r1[k0], r1[k0 + 1]),
                           pack2h(r0[k0 + 8], r0[k0 + 9]), pack2h(r1[k0 + 8], r1[k0 + 9]));
        }
    }
}

// LayerNorm + repack into next A fragments (fp16, registers only).
__device__ __forceinline__ void ln_repack(float (&d)[16][4],
                                          const float* __restrict__ bias,
                                          const float4* __restrict__ ge,
                                          uint32_t (&ah)[8][4],
                                          int t) {
    float s1a0 = 0.f, s1a1 = 0.f, s2a0 = 0.f, s2a1 = 0.f;
    float s1b0 = 0.f, s1b1 = 0.f, s2b0 = 0.f, s2b1 = 0.f;
#pragma unroll
    for (int j = 0; j < 16; j += 2) {
        {
            float2 bb = *(const float2*)(bias + 8 * j + 2 * t);
            float v0 = leaky_(d[j][0] + bb.x);
            float v1 = leaky_(d[j][1] + bb.y);
            float v2 = leaky_(d[j][2] + bb.x);
            float v3 = leaky_(d[j][3] + bb.y);
            d[j][0] = v0; d[j][1] = v1; d[j][2] = v2; d[j][3] = v3;
            s1a0 += v0 + v1;
            s2a0 = fmaf(v0, v0, s2a0); s2a0 = fmaf(v1, v1, s2a0);
            s1b0 += v2 + v3;
            s2b0 = fmaf(v2, v2, s2b0); s2b0 = fmaf(v3, v3, s2b0);
        }
        {
            int j1 = j + 1;
            float2 bb = *(const float2*)(bias + 8 * j1 + 2 * t);
            float v0 = leaky_(d[j1][0] + bb.x);
            float v1 = leaky_(d[j1][1] + bb.y);
            float v2 = leaky_(d[j1][2] + bb.x);
            float v3 = leaky_(d[j1][3] + bb.y);
            d[j1][0] = v0; d[j1][1] = v1; d[j1][2] = v2; d[j1][3] = v3;
            s1a1 += v0 + v1;
            s2a1 = fmaf(v0, v0, s2a1); s2a1 = fmaf(v1, v1, s2a1);
            s1b1 += v2 + v3;
            s2b1 = fmaf(v2, v2, s2b1); s2b1 = fmaf(v3, v3, s2b1);
        }
    }
    float s1a = s1a0 + s1a1, s2a = s2a0 + s2a1;
    float s1b = s1b0 + s1b1, s2b = s2b0 + s2b1;
#pragma unroll
    for (int off = 1; off <= 2; off <<= 1) {
        s1a += __shfl_xor_sync(0xffffffffu, s1a, off);
        s2a += __shfl_xor_sync(0xffffffffu, s2a, off);
        s1b += __shfl_xor_sync(0xffffffffu, s1b, off);
        s2b += __shfl_xor_sync(0xffffffffu, s2b, off);
    }
    float mua = s1a * (1.f / 128.f);
    float rsa = rsqrtf(fmaxf(s2a * (1.f / 128.f) - mua * mua, 0.f) + EPS_);
    float mub = s1b * (1.f / 128.f);
    float rsb = rsqrtf(fmaxf(s2b * (1.f / 128.f) - mub * mub, 0.f) + EPS_);
#pragma unroll
    for (int s = 0; s < 8; s++) {
        int j0 = 2 * s, j1 = 2 * s + 1;
        float4 A = ge[4 * j0 + t];
        float4 B = ge[4 * j1 + t];
        ah[s][0] = pack2h((d[j0][0] - mua) * rsa * A.x + A.z,
                          (d[j0][1] - mua) * rsa * A.y + A.w);
        ah[s][1] = pack2h((d[j0][2] - mub) * rsb * A.x + A.z,
                          (d[j0][3] - mub) * rsb * A.y + A.w);
        ah[s][2] = pack2h((d[j1][0] - mua) * rsa * B.x + B.z,
                          (d[j1][1] - mua) * rsa * B.y + B.w);
        ah[s][3] = pack2h((d[j1][2] - mub) * rsb * B.x + B.z,
                          (d[j1][3] - mub) * rsb * B.y + B.w);
    }
}

__global__ __launch_bounds__(NTH_, 1)
void film_mma_kernel(const float* __restrict__ b0, const float* __restrict__ g0,
                     const float* __restrict__ be0,
                     const float* __restrict__ b1, const float* __restrict__ g1,
                     const float* __restrict__ be1,
                     const float* __restrict__ b2,
                     float* __restrict__ out) {
    extern __shared__ char sp[];
    uint4* f0 = (uint4*)(sp + SM_W0);
    uint4* f1 = (uint4*)(sp + SM_W1);
    uint4* f2 = (uint4*)(sp + SM_W2);
    float* sB = (float*)(sp + SM_B);
    float4* sGE0 = (float4*)(sp + SM_GE0);
    float4* sGE1 = (float4*)(sp + SM_GE1);

    const int tid  = threadIdx.x;
    const int lane = tid & 31;
    const int wid  = tid >> 5;
    const int o    = blockIdx.y;
    const int g    = lane >> 2;
    const int t    = lane & 3;

    // ---- stage pre-converted weight fragments (coalesced uint4 copy) ----
    for (int i = tid; i < 4 * 8 * 32; i += NTH_) f0[i] = g_wf0[o][i];
    for (int i = tid; i < 8 * 8 * 32; i += NTH_) f1[i] = g_wf1[o][i];
    for (int i = tid; i < 8 * 32; i += NTH_)     f2[i] = g_wf2[o][i];
    if (tid < H_) {
        sB[tid]        = b0[o * H_ + tid];
        sB[H_ + tid]   = b1[o * H_ + tid];
        if (tid < F2_) sB[2 * H_ + tid] = b2[o * F2_ + tid];
    }
    if (tid < 64) {
        sGE0[tid] = make_float4(g0[o * H_ + 2 * tid], g0[o * H_ + 2 * tid + 1],
                                be0[o * H_ + 2 * tid], be0[o * H_ + 2 * tid + 1]);
        sGE1[tid] = make_float4(g1[o * H_ + 2 * tid], g1[o * H_ + 2 * tid + 1],
                                be1[o * H_ + 2 * tid], be1[o * H_ + 2 * tid + 1]);
    }
    __syncthreads();

    float d[16][4];
    uint32_t ah[8][4];
    uint32_t* scrh = (uint32_t*)g_scrh4 + ((size_t)o * NT_ * 8);

#pragma unroll 1
    for (int it = 0; it < TILES_; it++) {
        const int mt = (blockIdx.x * TILES_ + it) * 256 + wid * 16;

        // ---- load x fragments (coalesced uint4) ----
        {
            const uint4* xf = g_xf + ((size_t)(mt >> 4)) * 128 + lane;
#pragma unroll
            for (int s = 0; s < 4; s++) {
                uint4 v = xf[s * 32];
                ah[s][0] = v.x; ah[s][1] = v.y; ah[s][2] = v.z; ah[s][3] = v.w;
            }
        }

        // ---- GEMM0: M16 N128 K64 ----
#pragma unroll
        for (int j = 0; j < 16; j++)
#pragma unroll
            for (int q = 0; q < 4; q++) d[j][q] = 0.f;
#pragma unroll
        for (int s = 0; s < 4; s++) {
#pragma unroll
            for (int jp = 0; jp < 8; jp++) {
                uint4 b = f0[(s * 8 + jp) * 32 + lane];
                MMA2(d[2 * jp],     ah[s], b.x, b.y);
                MMA2(d[2 * jp + 1], ah[s], b.z, b.w);
            }
        }
        ln_repack(d, sB, sGE0, ah, t);

        // ---- GEMM1: M16 N128 K128 ----
#pragma unroll
        for (int j = 0; j < 16; j++)
#pragma unroll
            for (int q = 0; q < 4; q++) d[j][q] = 0.f;
#pragma unroll
        for (int s = 0; s < 8; s++) {
#pragma unroll
            for (int jp = 0; jp < 8; jp++) {
                uint4 b = f1[(s * 8 + jp) * 32 + lane];
                MMA2(d[2 * jp],     ah[s], b.x, b.y);
                MMA2(d[2 * jp + 1], ah[s], b.z, b.w);
            }
        }
        ln_repack(d, sB + H_, sGE1, ah, t);

        // ---- GEMM2: M16 N16 K128 ----
#pragma unroll
        for (int j = 0; j < 2; j++)
#pragma unroll
            for (int q = 0; q < 4; q++) d[j][q] = 0.f;
#pragma unroll
        for (int s = 0; s < 8; s++) {
            uint4 b = f2[s * 32 + lane];
            MMA2(d[0], ah[s], b.x, b.y);
            MMA2(d[1], ah[s], b.z, b.w);
        }

        // ---- output: leaky(D + b2) -> fp16 scratch [o][t][f] ----
        {
            const float* b2s = sB + 2 * H_;
#pragma unroll
            for (int j = 0; j < 2; j++) {
                int f = 8 * j + 2 * t;
                float2 bb = *(const float2*)(b2s + f);
                uint32_t pa = pack2h(leaky_(d[j][0] + bb.x), leaky_(d[j][1] + bb.y));
                uint32_t pb = pack2h(leaky_(d[j][2] + bb.x), leaky_(d[j][3] + bb.y));
                scrh[(size_t)(mt + g) * 8 + 4 * j + t]     = pa;
                scrh[(size_t)(mt + g + 8) * 8 + 4 * j + t] = pb;
            }
        }
    }

    // ================= decoupled-completion transpose =================
    // Last of the 16 o-CTAs for this token column transposes 512 tokens:
    // fp16 scratch [o][t][f] -> fp32 out [t][f][o].
    __threadfence();            // make this CTA's scratch writes device-visible
    __shared__ int s_prev;
    __syncthreads();            // all threads fenced before the arrival
    if (tid == 0) s_prev = atomicAdd(&g_cnt[blockIdx.x], 1);
    __syncthreads();
    if (s_prev != O_ - 1) return;
    __threadfence();            // order the counter read before scratch reads

    float* trsm = (float*)sp;   // reuse weight SMEM as staging (64 tok x 260)
    uint4* out4 = (uint4*)out;
#pragma unroll 1
    for (int c = 0; c < 8; c++) {
        const int t0c = blockIdx.x * (TILES_ * 256) + c * 64;
        // load: 16 o x 64 tok x 2 halves = 2048 uint4; 512 thr -> 4 each
#pragma unroll
        for (int p = 0; p < 4; p++) {
            int idx = p * 512 + tid;
            int oo = idx >> 7;
            int inner = idx & 127;
            int tt = inner >> 1, hf = (inner & 1) * 8;
            uint4 v = g_scrh4[((size_t)oo * NT_ + t0c + tt) * 2 + (inner & 1)];
            float* base = &trsm[tt * 260 + hf * 16 + oo];
            float2 a0 = __half22float2(*(__half2*)&v.x);
            float2 a1 = __half22float2(*(__half2*)&v.y);
            float2 a2 = __half22float2(*(__half2*)&v.z);
            float2 a3 = __half22float2(*(__half2*)&v.w);
            base[0]   = a0.x; base[16]  = a0.y;
            base[32]  = a1.x; base[48]  = a1.y;
            base[64]  = a2.x; base[80]  = a2.y;
            base[96]  = a3.x; base[112] = a3.y;
        }
        __syncthreads();
        // store: 64 tok x 64 uint4, fully contiguous per token row
#pragma unroll
        for (int p = 0; p < 8; p++) {
            int idx = p * 512 + tid;
            int tt = idx >> 6, inner = idx & 63;
            const float* s = &trsm[tt * 260 + inner * 4];
            out4[(size_t)(t0c + tt) * 64 + inner] =
                make_uint4(__float_as_uint(s[0]), __float_as_uint(s[1]),
                           __float_as_uint(s[2]), __float_as_uint(s[3]));
        }
        __syncthreads();
    }
}

extern "C" void kernel_launch(void* const* d_in, const int* in_sizes, int n_in,
                              void* d_out, int out_size) {
    const float* x   = (const float*)d_in[0];
    const float* W0  = (const float*)d_in[1];
    const float* b0  = (const float*)d_in[2];
    const float* g0  = (const float*)d_in[3];
    const float* be0 = (const float*)d_in[4];
    const float* W1  = (const float*)d_in[5];
    const float* b1  = (const float*)d_in[6];
    const float* g1  = (const float*)d_in[7];
    const float* be1 = (const float*)d_in[8];
    const float* W2  = (const float*)d_in[9];
    const float* b2  = (const float*)d_in[10];
    float* out = (float*)d_out;

    cudaFuncSetAttribute(film_mma_kernel,
                         cudaFuncAttributeMaxDynamicSharedMemorySize, SMEM_BYTES);
    cudaFuncSetAttribute(film_mma_kernel,
                         cudaFuncAttributePreferredSharedMemoryCarveout, 100);

    film_prep_kernel<<<64 + NT_ / 64, 256>>>(W0, W1, W2, x);
    dim3 grid(NT_ / (TILES_ * 256), O_);   // (64, 16)
    film_mma_kernel<<<grid, NTH_, SMEM_BYTES>>>(b0, g0, be0, b1, g1, be1, b2, out);
}

// round 17
// speedup vs baseline: 1.1574x; 1.1574x over previous
#include <cuda_runtime.h>
#include <cuda_fp16.h>
#include <cstdint>

#define H_     128
#define CIN_   64
#define O_     16
#define F2_    16
#define NT_    32768
#define TILES_ 2
#define NTH_   512
#define EPS_   1e-5f
#define SLOPE_ 0.01f

// ---- device scratch (static allocation; no runtime mallocs) ----
__device__ uint4 g_wf0[O_][4 * 8 * 32];               // weight fragments
__device__ uint4 g_wf1[O_][8 * 8 * 32];
__device__ uint4 g_wf2[O_][8 * 32];
__device__ uint4 g_xf[(size_t)(NT_ / 16) * 128];      // x fragments, 4MB
__device__ uint4 g_scrh4[(size_t)O_ * NT_ * 2];       // fp16 scratch [o][t][f], 16MB

// ---- main-kernel shared memory byte offsets ----
#define SM_W0  0          // [4][8][32] uint4 = 16384
#define SM_W1  16384      // [8][8][32] uint4 = 32768
#define SM_W2  49152      // [8][1][32] uint4 = 4096
#define SM_B   53248      // b0(128), b1(128), b2(16)
#define SM_GE0 54400      // 64 x float4
#define SM_GE1 55424      // 64 x float4
#define SMEM_BYTES 56448

__device__ __forceinline__ float leaky_(float v) { return fmaxf(v, SLOPE_ * v); }

__device__ __forceinline__ uint32_t pack2h(float y0, float y1) {
    uint32_t h;
    asm("cvt.rn.f16x2.f32 %0, %1, %2;" : "=r"(h) : "f"(y1), "f"(y0));
    return h;
}

#define MMA2(dd, aa, b0, b1)                                                   \
    asm volatile("mma.sync.aligned.m16n8k16.row.col.f32.f16.f16.f32 "         \
                 "{%0,%1,%2,%3}, {%4,%5,%6,%7}, {%8,%9}, {%0,%1,%2,%3};"      \
                 : "+f"((dd)[0]), "+f"((dd)[1]), "+f"((dd)[2]), "+f"((dd)[3]) \
                 : "r"((aa)[0]), "r"((aa)[1]), "r"((aa)[2]), "r"((aa)[3]),    \
                   "r"(b0), "r"(b1))

// ---------- fused prep kernel ----------
// blocks [0,64): weight fragment conversion (4 parts per o)
// blocks [64,576): x conversion (64 tokens per block)
__global__ __launch_bounds__(256, 1)
void film_prep_kernel(const float* __restrict__ W0, const float* __restrict__ W1,
                      const float* __restrict__ W2, const float* __restrict__ x) {
    const int tid = threadIdx.x;
    if (blockIdx.x < 64) {
        const int o = blockIdx.x >> 2;
        const int part = blockIdx.x & 3;
        const float* w0 = W0 + (size_t)o * H_ * CIN_;
        {
            int i = part * 256 + tid;
            int ln = i & 31, jp = (i >> 5) & 7, ss = i >> 8;
            int gg = ln >> 2, tt = ln & 3;
            int n0 = 8 * (2 * jp) + gg, n1 = n0 + 8, k0 = 16 * ss + 2 * tt;
            g_wf0[o][i] = make_uint4(pack2h(w0[n0 * 64 + k0],     w0[n0 * 64 + k0 + 1]),
                                     pack2h(w0[n0 * 64 + k0 + 8], w0[n0 * 64 + k0 + 9]),
                                     pack2h(w0[n1 * 64 + k0],     w0[n1 * 64 + k0 + 1]),
                                     pack2h(w0[n1 * 64 + k0 + 8], w0[n1 * 64 + k0 + 9]));
        }
        const float* w1 = W1 + (size_t)o * H_ * H_;
        for (int i = part * 512 + tid; i < (part + 1) * 512; i += 256) {
            int ln = i & 31, jp = (i >> 5) & 7, ss = i >> 8;
            int gg = ln >> 2, tt = ln & 3;
            int n0 = 8 * (2 * jp) + gg, n1 = n0 + 8, k0 = 16 * ss + 2 * tt;
            g_wf1[o][i] = make_uint4(pack2h(w1[n0 * 128 + k0],     w1[n0 * 128 + k0 + 1]),
                                     pack2h(w1[n0 * 128 + k0 + 8], w1[n0 * 128 + k0 + 9]),
                                     pack2h(w1[n1 * 128 + k0],     w1[n1 * 128 + k0 + 1]),
                                     pack2h(w1[n1 * 128 + k0 + 8], w1[n1 * 128 + k0 + 9]));
        }
        const float* w2 = W2 + (size_t)o * F2_ * H_;
        if (part == 0) {
            int i = tid;
            int ln = i & 31, ss = i >> 5;
            int gg = ln >> 2, tt = ln & 3;
            int n0 = gg, n1 = gg + 8, k0 = 16 * ss + 2 * tt;
            g_wf2[o][i] = make_uint4(pack2h(w2[n0 * 128 + k0],     w2[n0 * 128 + k0 + 1]),
                                     pack2h(w2[n0 * 128 + k0 + 8], w2[n0 * 128 + k0 + 9]),
                                     pack2h(w2[n1 * 128 + k0],     w2[n1 * 128 + k0 + 1]),
                                     pack2h(w2[n1 * 128 + k0 + 8], w2[n1 * 128 + k0 + 9]));
        }
    } else {
        // ---- x conversion: 64 tokens per block, row-major fp32 -> fragment fp16 ----
        __shared__ float sx[64 * 64];
        const int blk = blockIdx.x - 64;
        const float4* x4 = (const float4*)(x + (size_t)blk * 64 * 64);
        float4* s4 = (float4*)sx;
#pragma unroll
        for (int p = 0; p < 4; p++) s4[p * 256 + tid] = x4[p * 256 + tid];
        __syncthreads();
        const int tb0 = blk * 4;
#pragma unroll
        for (int p = 0; p < 2; p++) {
            int idx = p * 256 + tid;
            int tb = idx >> 7, rest = idx & 127, s = rest >> 5, lane = rest & 31;
            int g = lane >> 2, t = lane & 3;
            int k0 = 16 * s + 2 * t;
            const float* r0 = sx + (tb * 16 + g) * 64;
            const float* r1 = sx + (tb * 16 + g + 8) * 64;
            g_xf[(size_t)(tb0 + tb) * 128 + s * 32 + lane] =
                make_uint4(pack2h(r0[k0], r0[k0 + 1]),     pack2h(r1[k0], r1[k0 + 1]),
                           pack2h(r0[k0 + 8], r0[k0 + 9]), pack2h(r1[k0 + 8], r1[k0 + 9]));
        }
    }
}

// LayerNorm + repack into next A fragments (fp16, registers only).
__device__ __forceinline__ void ln_repack(float (&d)[16][4],
                                          const float* __restrict__ bias,
                                          const float4* __restrict__ ge,
                                          uint32_t (&ah)[8][4],
                                          int t) {
    float s1a0 = 0.f, s1a1 = 0.f, s2a0 = 0.f, s2a1 = 0.f;
    float s1b0 = 0.f, s1b1 = 0.f, s2b0 = 0.f, s2b1 = 0.f;
#pragma unroll
    for (int j = 0; j < 16; j += 2) {
        {
            float2 bb = *(const float2*)(bias + 8 * j + 2 * t);
            float v0 = leaky_(d[j][0] + bb.x);
            float v1 = leaky_(d[j][1] + bb.y);
            float v2 = leaky_(d[j][2] + bb.x);
            float v3 = leaky_(d[j][3] + bb.y);
            d[j][0] = v0; d[j][1] = v1; d[j][2] = v2; d[j][3] = v3;
            s1a0 += v0 + v1;
            s2a0 = fmaf(v0, v0, s2a0); s2a0 = fmaf(v1, v1, s2a0);
            s1b0 += v2 + v3;
            s2b0 = fmaf(v2, v2, s2b0); s2b0 = fmaf(v3, v3, s2b0);
        }
        {
            int j1 = j + 1;
            float2 bb = *(const float2*)(bias + 8 * j1 + 2 * t);
            float v0 = leaky_(d[j1][0] + bb.x);
            float v1 = leaky_(d[j1][1] + bb.y);
            float v2 = leaky_(d[j1][2] + bb.x);
            float v3 = leaky_(d[j1][3] + bb.y);
            d[j1][0] = v0; d[j1][1] = v1; d[j1][2] = v2; d[j1][3] = v3;
            s1a1 += v0 + v1;
            s2a1 = fmaf(v0, v0, s2a1); s2a1 = fmaf(v1, v1, s2a1);
            s1b1 += v2 + v3;
            s2b1 = fmaf(v2, v2, s2b1); s2b1 = fmaf(v3, v3, s2b1);
        }
    }
    float s1a = s1a0 + s1a1, s2a = s2a0 + s2a1;
    float s1b = s1b0 + s1b1, s2b = s2b0 + s2b1;
#pragma unroll
    for (int off = 1; off <= 2; off <<= 1) {
        s1a += __shfl_xor_sync(0xffffffffu, s1a, off);
        s2a += __shfl_xor_sync(0xffffffffu, s2a, off);
        s1b += __shfl_xor_sync(0xffffffffu, s1b, off);
        s2b += __shfl_xor_sync(0xffffffffu, s2b, off);
    }
    float mua = s1a * (1.f / 128.f);
    float rsa = rsqrtf(fmaxf(s2a * (1.f / 128.f) - mua * mua, 0.f) + EPS_);
    float mub = s1b * (1.f / 128.f);
    float rsb = rsqrtf(fmaxf(s2b * (1.f / 128.f) - mub * mub, 0.f) + EPS_);
#pragma unroll
    for (int s = 0; s < 8; s++) {
        int j0 = 2 * s, j1 = 2 * s + 1;
        float4 A = ge[4 * j0 + t];
        float4 B = ge[4 * j1 + t];
        ah[s][0] = pack2h((d[j0][0] - mua) * rsa * A.x + A.z,
                          (d[j0][1] - mua) * rsa * A.y + A.w);
        ah[s][1] = pack2h((d[j0][2] - mub) * rsb * A.x + A.z,
                          (d[j0][3] - mub) * rsb * A.y + A.w);
        ah[s][2] = pack2h((d[j1][0] - mua) * rsa * B.x + B.z,
                          (d[j1][1] - mua) * rsa * B.y + B.w);
        ah[s][3] = pack2h((d[j1][2] - mub) * rsb * B.x + B.z,
                          (d[j1][3] - mub) * rsb * B.y + B.w);
    }
}

__global__ __launch_bounds__(NTH_, 1)
void film_mma_kernel(const float* __restrict__ b0, const float* __restrict__ g0,
                     const float* __restrict__ be0,
                     const float* __restrict__ b1, const float* __restrict__ g1,
                     const float* __restrict__ be1,
                     const float* __restrict__ b2) {
    extern __shared__ char sp[];
    uint4* f0 = (uint4*)(sp + SM_W0);
    uint4* f1 = (uint4*)(sp + SM_W1);
    uint4* f2 = (uint4*)(sp + SM_W2);
    float* sB = (float*)(sp + SM_B);
    float4* sGE0 = (float4*)(sp + SM_GE0);
    float4* sGE1 = (float4*)(sp + SM_GE1);

    const int tid  = threadIdx.x;
    const int lane = tid & 31;
    const int wid  = tid >> 5;
    const int o    = blockIdx.y;
    const int g    = lane >> 2;
    const int t    = lane & 3;

    // ---- stage pre-converted weight fragments (coalesced uint4 copy) ----
    for (int i = tid; i < 4 * 8 * 32; i += NTH_) f0[i] = g_wf0[o][i];
    for (int i = tid; i < 8 * 8 * 32; i += NTH_) f1[i] = g_wf1[o][i];
    for (int i = tid; i < 8 * 32; i += NTH_)     f2[i] = g_wf2[o][i];
    if (tid < H_) {
        sB[tid]        = b0[o * H_ + tid];
        sB[H_ + tid]   = b1[o * H_ + tid];
        if (tid < F2_) sB[2 * H_ + tid] = b2[o * F2_ + tid];
    }
    if (tid < 64) {
        sGE0[tid] = make_float4(g0[o * H_ + 2 * tid], g0[o * H_ + 2 * tid + 1],
                                be0[o * H_ + 2 * tid], be0[o * H_ + 2 * tid + 1]);
        sGE1[tid] = make_float4(g1[o * H_ + 2 * tid], g1[o * H_ + 2 * tid + 1],
                                be1[o * H_ + 2 * tid], be1[o * H_ + 2 * tid + 1]);
    }
    __syncthreads();

    float d[16][4];
    uint32_t ah[8][4];
    uint32_t* scrh = (uint32_t*)g_scrh4 + ((size_t)o * NT_ * 8);

#pragma unroll 1
    for (int it = 0; it < TILES_; it++) {
        const int mt = (blockIdx.x * TILES_ + it) * 256 + wid * 16;

        // ---- load x fragments (coalesced uint4) ----
        {
            const uint4* xf = g_xf + ((size_t)(mt >> 4)) * 128 + lane;
#pragma unroll
            for (int s = 0; s < 4; s++) {
                uint4 v = xf[s * 32];
                ah[s][0] = v.x; ah[s][1] = v.y; ah[s][2] = v.z; ah[s][3] = v.w;
            }
        }

        // ---- GEMM0: M16 N128 K64 ----
#pragma unroll
        for (int j = 0; j < 16; j++)
#pragma unroll
            for (int q = 0; q < 4; q++) d[j][q] = 0.f;
#pragma unroll
        for (int s = 0; s < 4; s++) {
#pragma unroll
            for (int jp = 0; jp < 8; jp++) {
                uint4 b = f0[(s * 8 + jp) * 32 + lane];
                MMA2(d[2 * jp],     ah[s], b.x, b.y);
                MMA2(d[2 * jp + 1], ah[s], b.z, b.w);
            }
        }
        ln_repack(d, sB, sGE0, ah, t);

        // ---- GEMM1: M16 N128 K128 ----
#pragma unroll
        for (int j = 0; j < 16; j++)
#pragma unroll
            for (int q = 0; q < 4; q++) d[j][q] = 0.f;
#pragma unroll
        for (int s = 0; s < 8; s++) {
#pragma unroll
            for (int jp = 0; jp < 8; jp++) {
                uint4 b = f1[(s * 8 + jp) * 32 + lane];
                MMA2(d[2 * jp],     ah[s], b.x, b.y);
                MMA2(d[2 * jp + 1], ah[s], b.z, b.w);
            }
        }
        ln_repack(d, sB + H_, sGE1, ah, t);

        // ---- GEMM2: M16 N16 K128 ----
#pragma unroll
        for (int j = 0; j < 2; j++)
#pragma unroll
            for (int q = 0; q < 4; q++) d[j][q] = 0.f;
#pragma unroll
        for (int s = 0; s < 8; s++) {
            uint4 b = f2[s * 32 + lane];
            MMA2(d[0], ah[s], b.x, b.y);
            MMA2(d[1], ah[s], b.z, b.w);
        }

        // ---- output: leaky(D + b2) -> fp16 scratch [o][t][f] ----
        {
            const float* b2s = sB + 2 * H_;
#pragma unroll
            for (int j = 0; j < 2; j++) {
                int f = 8 * j + 2 * t;
                float2 bb = *(const float2*)(b2s + f);
                uint32_t pa = pack2h(leaky_(d[j][0] + bb.x), leaky_(d[j][1] + bb.y));
                uint32_t pb = pack2h(leaky_(d[j][2] + bb.x), leaky_(d[j][3] + bb.y));
                scrh[(size_t)(mt + g) * 8 + 4 * j + t]     = pa;
                scrh[(size_t)(mt + g + 8) * 8 + 4 * j + t] = pb;
            }
        }
    }
}

// ---------- transpose kernel: fp16 scratch [o][t][f] -> fp32 out [t][f][o] ----------
#define TT_ 32      // tokens per block
__global__ __launch_bounds__(256, 1)
void film_tr_kernel(float* __restrict__ out) {
    __shared__ float sm[TT_ * 260];   // [t][f*16+o], padded row stride 260
    const int tid = threadIdx.x;
    const int t0 = blockIdx.x * TT_;

    // load: per o-slice, 32 tok x 16 f halves = 64 uint4; 16 o x 64 = 1024
#pragma unroll
    for (int p = 0; p < 4; p++) {
        int idx = p * 256 + tid;
        int o = idx >> 6;
        int inner = idx & 63;
        int t = inner >> 1, hf = (inner & 1) * 8;
        uint4 v = g_scrh4[((size_t)o * NT_ + t0 + t) * 2 + (inner & 1)];
        float* base = &sm[t * 260 + hf * 16 + o];
        float2 a0 = __half22float2(*(__half2*)&v.x);
        float2 a1 = __half22float2(*(__half2*)&v.y);
        float2 a2 = __half22float2(*(__half2*)&v.z);
        float2 a3 = __half22float2(*(__half2*)&v.w);
        base[0]   = a0.x; base[16]  = a0.y;
        base[32]  = a1.x; base[48]  = a1.y;
        base[64]  = a2.x; base[80]  = a2.y;
        base[96]  = a3.x; base[112] = a3.y;
    }
    __syncthreads();

    // store: out token row (256 floats) fully contiguous
    uint4* out4 = (uint4*)out;
#pragma unroll
    for (int p = 0; p < 8; p++) {
        int idx = p * 256 + tid;
        int t = idx >> 6, inner = idx & 63;
        const float* s = &sm[t * 260 + inner * 4];
        out4[(size_t)(t0 + t) * 64 + inner] =
            make_uint4(__float_as_uint(s[0]), __float_as_uint(s[1]),
                       __float_as_uint(s[2]), __float_as_uint(s[3]));
    }
}

extern "C" void kernel_launch(void* const* d_in, const int* in_sizes, int n_in,
                              void* d_out, int out_size) {
    const float* x   = (const float*)d_in[0];
    const float* W0  = (const float*)d_in[1];
    const float* b0  = (const float*)d_in[2];
    const float* g0  = (const float*)d_in[3];
    const float* be0 = (const float*)d_in[4];
    const float* W1  = (const float*)d_in[5];
    const float* b1  = (const float*)d_in[6];
    const float* g1  = (const float*)d_in[7];
    const float* be1 = (const float*)d_in[8];
    const float* W2  = (const float*)d_in[9];
    const float* b2  = (const float*)d_in[10];
    float* out = (float*)d_out;

    cudaFuncSetAttribute(film_mma_kernel,
                         cudaFuncAttributeMaxDynamicSharedMemorySize, SMEM_BYTES);
    cudaFuncSetAttribute(film_mma_kernel,
                         cudaFuncAttributePreferredSharedMemoryCarveout, 100);

    film_prep_kernel<<<64 + NT_ / 64, 256>>>(W0, W1, W2, x);
    dim3 grid(NT_ / (TILES_ * 256), O_);   // (64, 16)
    film_mma_kernel<<<grid, NTH_, SMEM_BYTES>>>(b0, g0, be0, b1, g1, be1, b2);
    film_tr_kernel<<<NT_ / TT_, 256>>>(out);
}